// round 14
// baseline (speedup 1.0000x reference)
#include <cuda_runtime.h>
#include <math.h>
#include <stdint.h>

#define ROWS    32768
#define COLS    1024
#define D_IN    256
#define D_OUT   256
#define D_CTRL  1024
#define D_CIN   1280      // D_IN + COLS
#define HEADSZ  1030      // COLS + 1 + 1 + 3 + 1
#define N_PAR   4108      // 2*HEADSZ + 2*COLS
#define NBF     1024      // blocks in final pass (single wave)
#define RPB     32        // rows per block in final pass
#define SIM_GRID 592      // 148 SMs x 4 resident blocks
#define SIM_CHUNKS (ROWS / 32)   // 1024 chunks of 32 rows

// ---------------- device scratch (static: no allocations allowed) -----------
__device__ float g_h[D_CTRL];
__device__ float g_p[N_PAR];
__device__ float g_krn[COLS], g_kwn[COLS], g_e[COLS], g_a[COLS];
__device__ float g_scal[12];          // per head: beta, g, s0, s1, s2, gamma
__device__ float g_red[4];            // sumexp_r, sumexp_w, powsum_r, powsum_w
__device__ unsigned int g_ctr;        // k_sim work-stealing counter
__device__ float g_z[2][ROWS];        // exp(beta*cos - beta) per head
__device__ float g_wpow[2][ROWS];     // pre-normalization sharpened weights
__device__ float g_part[NBF * COLS];  // read_vec block partials (4 MB)

// ---------------- helpers ----------------------------------------------------
__device__ __forceinline__ float sigmoidf_(float x) { return 1.f / (1.f + expf(-x)); }
__device__ __forceinline__ float softplusf_(float x) { return x > 20.f ? x : log1pf(expf(x)); }

__device__ __forceinline__ void pdl_launch() {
    asm volatile("griddepcontrol.launch_dependents;");
}
__device__ __forceinline__ void pdl_wait() {
    asm volatile("griddepcontrol.wait;" ::: "memory");
}

__device__ __forceinline__ float warp_sum(float v) {
    #pragma unroll
    for (int o = 16; o; o >>= 1) v += __shfl_down_sync(0xffffffffu, v, o);
    return v;
}

// block-wide sum for 1024 threads; red must be shared float[33]
__device__ float block_sum_1024(float v, float* red) {
    int t = threadIdx.x;
    v = warp_sum(v);
    if ((t & 31) == 0) red[t >> 5] = v;
    __syncthreads();
    if (t < 32) {
        float u = red[t];
        u = warp_sum(u);
        if (t == 0) red[32] = u;
    }
    __syncthreads();
    return red[32];
}

// ---------------- K1: h = Wc @ [x; read_prev] + bc --------------------------
__global__ void k_gemv_h(const float* __restrict__ x, const float* __restrict__ rp,
                         const float* __restrict__ Wc, const float* __restrict__ bc) {
    pdl_launch();
    int warp = (blockIdx.x * blockDim.x + threadIdx.x) >> 5;
    int lane = threadIdx.x & 31;
    if (warp >= D_CTRL) return;
    const float4* W4 = (const float4*)(Wc + (size_t)warp * D_CIN);
    const float4* x4 = (const float4*)x;
    const float4* r4 = (const float4*)rp;
    float s = 0.f;
    #pragma unroll
    for (int k = 0; k < 10; k++) {
        int c = lane + 32 * k;                 // float4 index 0..319
        float4 w = W4[c];
        float4 v = (c < 64) ? x4[c] : r4[c - 64];
        s += w.x * v.x + w.y * v.y + w.z * v.z + w.w * v.w;
    }
    s = warp_sum(s);
    if (lane == 0) g_h[warp] = s + bc[warp];
}

// ---------------- K2: p = Wp @ h + bp ; saida = sigmoid(Wo @ h + bo) ---------
// PDL: loads ALL weight regs before waiting on gemv_h.
__global__ void k_gemv_p(const float* __restrict__ Wp, const float* __restrict__ bp,
                         const float* __restrict__ Wo, const float* __restrict__ bo,
                         float* __restrict__ o_saida) {
    int warp = (blockIdx.x * blockDim.x + threadIdx.x) >> 5;
    int lane = threadIdx.x & 31;
    if (warp >= N_PAR + D_OUT) { pdl_wait(); return; }
    const float4* W4 = (warp < N_PAR)
        ? (const float4*)(Wp + (size_t)warp * D_CTRL)
        : (const float4*)(Wo + (size_t)(warp - N_PAR) * D_CTRL);
    float4 w[8];
    #pragma unroll
    for (int k = 0; k < 8; k++) w[k] = __ldcs(&W4[lane + 32 * k]);

    pdl_wait();

    const float4* h4 = (const float4*)g_h;
    float s = 0.f;
    #pragma unroll
    for (int k = 0; k < 8; k++) {
        float4 v = h4[lane + 32 * k];
        s += w[k].x * v.x + w[k].y * v.y + w[k].z * v.z + w[k].w * v.w;
    }
    s = warp_sum(s);
    if (lane == 0) {
        if (warp < N_PAR) g_p[warp] = s + bp[warp];
        else o_saida[warp - N_PAR] = sigmoidf_(s + bo[warp - N_PAR]);
    }
}

// ---------------- K3: activations, key norm, scalars, reset reds + counter --
__global__ void k_activ() {
    pdl_launch();
    pdl_wait();
    __shared__ float red[33];
    int t = threadIdx.x;  // 1024 threads

    float kr = tanhf(g_p[t]);
    float nr = block_sum_1024(kr * kr, red);
    float kw = tanhf(g_p[HEADSZ + t]);
    float nw = block_sum_1024(kw * kw, red);

    g_krn[t] = kr / fmaxf(sqrtf(nr), 1e-12f);
    g_kwn[t] = kw / fmaxf(sqrtf(nw), 1e-12f);
    g_e[t]   = sigmoidf_(g_p[2 * HEADSZ + t]);
    g_a[t]   = tanhf(g_p[2 * HEADSZ + COLS + t]);

    if (t < 2) {
        int o = t * HEADSZ;
        float beta  = softplusf_(g_p[o + COLS]);
        float gg    = sigmoidf_(g_p[o + COLS + 1]);
        float a0 = g_p[o + COLS + 2], a1 = g_p[o + COLS + 3], a2 = g_p[o + COLS + 4];
        float m = fmaxf(a0, fmaxf(a1, a2));
        float e0 = expf(a0 - m), e1 = expf(a1 - m), e2 = expf(a2 - m);
        float inv = 1.f / (e0 + e1 + e2);
        float gamma = softplusf_(g_p[o + COLS + 5]) + 1.f;
        g_scal[t * 6 + 0] = beta;
        g_scal[t * 6 + 1] = gg;
        g_scal[t * 6 + 2] = e0 * inv;
        g_scal[t * 6 + 3] = e1 * inv;
        g_scal[t * 6 + 4] = e2 * inv;
        g_scal[t * 6 + 5] = gamma;
    }
    if (t < 4) g_red[t] = 0.f;
    if (t == 0) g_ctr = 0u;
}

// ---------------- K4: similarity pass — persistent, work-stealing -----------
// Champion inner loop (keys in smem, 4 rows/warp, k-unroll x2, 8 LDG.128 in
// flight). Grid 592 = exact residency; blocks steal 32-row chunks from a
// global counter -> no wave-quantization tail, per-CTA spread self-balances.
__global__ void __launch_bounds__(256) k_sim(const float* __restrict__ mem) {
    pdl_launch();
    pdl_wait();
    __shared__ float4 skr[256], skw[256];
    __shared__ float ser[8], sew[8];
    __shared__ unsigned int s_chunk;
    int t = threadIdx.x;
    skr[t] = ((const float4*)g_krn)[t];
    skw[t] = ((const float4*)g_kwn)[t];

    int warp = t >> 5, lane = t & 31;
    float br = g_scal[0], bw = g_scal[6];
    float sr = 0.f, sw = 0.f;   // lane-0 per-warp accumulators across chunks

    for (;;) {
        if (t == 0) s_chunk = atomicAdd(&g_ctr, 1u);
        __syncthreads();
        unsigned int chunk = s_chunk;
        if (chunk >= SIM_CHUNKS) break;
        int row0 = (int)chunk * 32 + warp * 4;
        const float4* m0 = (const float4*)mem + (size_t)row0 * 256;

        float dr[4], dw[4], ss[4];
        #pragma unroll
        for (int j = 0; j < 4; j++) { dr[j] = 0.f; dw[j] = 0.f; ss[j] = 0.f; }

        #pragma unroll
        for (int k = 0; k < 8; k += 2) {
            int c0 = lane + 32 * k, c1 = c0 + 32;
            float4 a[4][2];
            #pragma unroll
            for (int j = 0; j < 4; j++) {
                a[j][0] = __ldcs(&m0[(size_t)j * 256 + c0]);
                a[j][1] = __ldcs(&m0[(size_t)j * 256 + c1]);
            }
            float4 r0 = skr[c0], r1 = skr[c1];
            float4 w0 = skw[c0], w1 = skw[c1];
            #pragma unroll
            for (int j = 0; j < 4; j++) {
                float4 v = a[j][0];
                dr[j] += v.x * r0.x + v.y * r0.y + v.z * r0.z + v.w * r0.w;
                dw[j] += v.x * w0.x + v.y * w0.y + v.z * w0.z + v.w * w0.w;
                ss[j] += v.x * v.x + v.y * v.y + v.z * v.z + v.w * v.w;
                v = a[j][1];
                dr[j] += v.x * r1.x + v.y * r1.y + v.z * r1.z + v.w * r1.w;
                dw[j] += v.x * w1.x + v.y * w1.y + v.z * w1.z + v.w * w1.w;
                ss[j] += v.x * v.x + v.y * v.y + v.z * v.z + v.w * v.w;
            }
        }
        #pragma unroll
        for (int j = 0; j < 4; j++) {
            dr[j] = warp_sum(dr[j]);
            dw[j] = warp_sum(dw[j]);
            ss[j] = warp_sum(ss[j]);
        }
        if (lane == 0) {
            #pragma unroll
            for (int j = 0; j < 4; j++) {
                float inv = 1.f / fmaxf(sqrtf(ss[j]), 1e-12f);
                // z = beta*cos; subtract analytic bound beta (cos <= 1)
                float er = expf(br * dr[j] * inv - br);
                float ew = expf(bw * dw[j] * inv - bw);
                g_z[0][row0 + j] = er;
                g_z[1][row0 + j] = ew;
                sr += er; sw += ew;
            }
        }
        __syncthreads();   // all reads of s_chunk done before next overwrite
    }

    if (lane == 0) { ser[warp] = sr; sew[warp] = sw; }
    __syncthreads();
    if (t == 0) {
        float tsr = 0.f, tsw = 0.f;
        #pragma unroll
        for (int i = 0; i < 8; i++) { tsr += ser[i]; tsw += sew[i]; }
        atomicAdd(&g_red[0], tsr);
        atomicAdd(&g_red[1], tsw);
    }
}

// ---------------- K5: gate + circular shift + sharpening (both heads) -------
__global__ void k_shiftpow(const float* __restrict__ wpr, const float* __restrict__ wpw) {
    pdl_launch();   // k_final prologue reads only memoria
    __shared__ float red[8];
    int head = blockIdx.y;
    int i = blockIdx.x * 256 + threadIdx.x;
    const float* wprev = head ? wpw : wpr;
    int im = (i - 1) & (ROWS - 1), ip = (i + 1) & (ROWS - 1);
    float pvm = wprev[im], pv0 = wprev[i], pvp = wprev[ip];

    pdl_wait();

    const float* z = g_z[head];
    float invsum = 1.f / g_red[head];
    float gg = g_scal[head * 6 + 1];
    float s0 = g_scal[head * 6 + 2], s1 = g_scal[head * 6 + 3], s2 = g_scal[head * 6 + 4];
    float gamma = g_scal[head * 6 + 5];
    float omg = 1.f - gg;

    float wgm = gg * z[im] * invsum + omg * pvm;
    float wg0 = gg * z[i]  * invsum + omg * pv0;
    float wgp = gg * z[ip] * invsum + omg * pvp;
    float wt = s0 * wgm + s1 * wg0 + s2 * wgp;   // roll(+1)=i-1, roll(-1)=i+1
    float wp = powf(wt, gamma);
    g_wpow[head][i] = wp;

    wp = warp_sum(wp);
    if ((threadIdx.x & 31) == 0) red[threadIdx.x >> 5] = wp;
    __syncthreads();
    if (threadIdx.x == 0) {
        float s = 0.f;
        #pragma unroll
        for (int w = 0; w < 8; w++) s += red[w];
        atomicAdd(&g_red[2 + head], s);
    }
}

// ---------------- K6: final pass — single wave (1024 blocks, 32 rows) -------
// Champion pipeline, RPB=32: 1024 blocks <= residency (8/SM) -> one wave, no
// second-wave tail; g_part round-trip halves to 8 MB.
__global__ void __launch_bounds__(256) k_final(const float* __restrict__ mem,
                                               float* __restrict__ memnew,
                                               float* __restrict__ o_wr,
                                               float* __restrict__ o_ww) {
    int t = threadIdx.x;
    int row0 = blockIdx.x * RPB;
    const float4* m4 = (const float4*)mem + (size_t)row0 * 256 + t;
    float4* o4 = (float4*)memnew + (size_t)row0 * 256 + t;

    float4 buf[2][4];
    #pragma unroll
    for (int j = 0; j < 4; j++) buf[0][j] = __ldcs(m4 + (size_t)j * 256);

    pdl_wait();

    float inv_r = 1.f / (g_red[2] + 1e-8f);
    float inv_w = 1.f / (g_red[3] + 1e-8f);

    if (t < RPB) {
        int r = row0 + t;
        o_wr[r] = g_wpow[0][r] * inv_r;
        o_ww[r] = g_wpow[1][r] * inv_w;
    }

    float4 e = ((const float4*)g_e)[t];
    float4 a = ((const float4*)g_a)[t];
    float4 acc = make_float4(0.f, 0.f, 0.f, 0.f);

    #pragma unroll 2
    for (int r = 0; r < RPB; r += 4) {
        const int cur = (r >> 2) & 1, nxt = cur ^ 1;
        if (r + 4 < RPB) {
            #pragma unroll
            for (int j = 0; j < 4; j++)
                buf[nxt][j] = __ldcs(m4 + (size_t)(r + 4 + j) * 256);
        }
        #pragma unroll
        for (int j = 0; j < 4; j++) {
            int row = row0 + r + j;
            float wr = g_wpow[0][row] * inv_r;
            float ww = g_wpow[1][row] * inv_w;
            float4 m = buf[cur][j];
            float4 o;
            o.x = m.x * (1.f - ww * e.x) + ww * a.x;
            o.y = m.y * (1.f - ww * e.y) + ww * a.y;
            o.z = m.z * (1.f - ww * e.z) + ww * a.z;
            o.w = m.w * (1.f - ww * e.w) + ww * a.w;
            __stcs(o4 + (size_t)(r + j) * 256, o);
            acc.x += wr * m.x;
            acc.y += wr * m.y;
            acc.z += wr * m.z;
            acc.w += wr * m.w;
        }
    }
    ((float4*)g_part)[(size_t)blockIdx.x * 256 + t] = acc;
}

// ---------------- K7: reduce read_vec partials (NBF=1024) --------------------
__global__ void __launch_bounds__(256) k_rv(float* __restrict__ rv) {
    pdl_wait();
    __shared__ float4 sh[256];
    int b = blockIdx.x;      // 0..255
    int t = threadIdx.x;
    const float4* p4 = (const float4*)g_part;
    float4 s = make_float4(0.f, 0.f, 0.f, 0.f);
    #pragma unroll
    for (int i = 0; i < NBF / 256; i++) {
        float4 v = __ldcs(&p4[(size_t)(t + i * 256) * 256 + b]);
        s.x += v.x; s.y += v.y; s.z += v.z; s.w += v.w;
    }
    sh[t] = s;
    __syncthreads();
    #pragma unroll
    for (int off = 128; off >= 1; off >>= 1) {
        if (t < off) {
            float4 u = sh[t + off];
            sh[t].x += u.x; sh[t].y += u.y; sh[t].z += u.z; sh[t].w += u.w;
        }
        __syncthreads();
    }
    if (t == 0) ((float4*)rv)[b] = sh[0];
}

// ---------------- launcher ----------------------------------------------------
template <typename K, typename... Args>
static void launch_pdl(K kernel, dim3 grid, dim3 block, Args... args) {
    cudaLaunchConfig_t cfg = {};
    cfg.gridDim = grid;
    cfg.blockDim = block;
    cfg.dynamicSmemBytes = 0;
    cfg.stream = 0;
    cudaLaunchAttribute attr[1];
    attr[0].id = cudaLaunchAttributeProgrammaticStreamSerialization;
    attr[0].val.programmaticStreamSerializationAllowed = 1;
    cfg.attrs = attr;
    cfg.numAttrs = 1;
    cudaLaunchKernelEx(&cfg, kernel, args...);
}

extern "C" void kernel_launch(void* const* d_in, const int* in_sizes, int n_in,
                              void* d_out, int out_size) {
    const float* x   = (const float*)d_in[0];
    const float* mem = (const float*)d_in[1];
    const float* Wc  = (const float*)d_in[2];
    const float* bc  = (const float*)d_in[3];
    const float* Wp  = (const float*)d_in[4];
    const float* bp  = (const float*)d_in[5];
    const float* Wo  = (const float*)d_in[6];
    const float* bo  = (const float*)d_in[7];
    const float* rp  = (const float*)d_in[8];
    const float* wrp = (const float*)d_in[9];
    const float* wwp = (const float*)d_in[10];

    float* out     = (float*)d_out;
    float* o_saida = out;                                  // [256]
    float* o_mem   = out + D_OUT;                          // [32768*1024]
    float* o_rv    = o_mem + (size_t)ROWS * COLS;          // [1024]
    float* o_wr    = o_rv + COLS;                          // [32768]
    float* o_ww    = o_wr + ROWS;                          // [32768]

    k_gemv_h<<<D_CTRL / 8, 256>>>(x, rp, Wc, bc);
    launch_pdl(k_gemv_p, dim3((N_PAR + D_OUT + 7) / 8), dim3(256), Wp, bp, Wo, bo, o_saida);
    launch_pdl(k_activ, dim3(1), dim3(1024));
    launch_pdl(k_sim, dim3(SIM_GRID), dim3(256), mem);
    launch_pdl(k_shiftpow, dim3(ROWS / 256, 2), dim3(256), wrp, wwp);
    launch_pdl(k_final, dim3(NBF), dim3(256), mem, o_mem, o_wr, o_ww);
    launch_pdl(k_rv, dim3(COLS / 4), dim3(256), o_rv);
}

// round 15
// speedup vs baseline: 1.0283x; 1.0283x over previous
#include <cuda_runtime.h>
#include <math.h>
#include <stdint.h>

#define ROWS    32768
#define COLS    1024
#define D_IN    256
#define D_OUT   256
#define D_CTRL  1024
#define D_CIN   1280      // D_IN + COLS
#define HEADSZ  1030      // COLS + 1 + 1 + 3 + 1
#define N_PAR   4108      // 2*HEADSZ + 2*COLS
#define NBF     2048      // blocks in final pass
#define RPB     16        // rows per block in final pass

#define SIMB_ROWS 16                    // rows per k_sim block (2 per warp)
#define SIM_SMEM  (SIMB_ROWS * 4096 + 8192)   // 64KB data + 8KB keys = 73728

// ---------------- device scratch (static: no allocations allowed) -----------
__device__ float g_h[D_CTRL];
__device__ float g_p[N_PAR];
__device__ float g_krn[COLS], g_kwn[COLS], g_e[COLS], g_a[COLS];
__device__ float g_scal[12];          // per head: beta, g, s0, s1, s2, gamma
__device__ float g_red[4];            // sumexp_r, sumexp_w, powsum_r, powsum_w
__device__ float g_z[2][ROWS];        // exp(beta*cos - beta) per head
__device__ float g_wpow[2][ROWS];     // pre-normalization sharpened weights
__device__ float g_part[NBF * COLS];  // read_vec block partials (8 MB)

// ---------------- helpers ----------------------------------------------------
__device__ __forceinline__ float sigmoidf_(float x) { return 1.f / (1.f + expf(-x)); }
__device__ __forceinline__ float softplusf_(float x) { return x > 20.f ? x : log1pf(expf(x)); }

__device__ __forceinline__ void pdl_launch() {
    asm volatile("griddepcontrol.launch_dependents;");
}
__device__ __forceinline__ void pdl_wait() {
    asm volatile("griddepcontrol.wait;" ::: "memory");
}
__device__ __forceinline__ uint32_t smem_u32(const void* p) {
    uint32_t a;
    asm("{ .reg .u64 t; cvta.to.shared.u64 t, %1; cvt.u32.u64 %0, t; }" : "=r"(a) : "l"(p));
    return a;
}
__device__ __forceinline__ void cp_async16(uint32_t dst_s, const void* src_g) {
    asm volatile("cp.async.cg.shared.global [%0], [%1], 16;"
                 :: "r"(dst_s), "l"(src_g) : "memory");
}

__device__ __forceinline__ float warp_sum(float v) {
    #pragma unroll
    for (int o = 16; o; o >>= 1) v += __shfl_down_sync(0xffffffffu, v, o);
    return v;
}

// block-wide sum for 1024 threads; red must be shared float[33]
__device__ float block_sum_1024(float v, float* red) {
    int t = threadIdx.x;
    v = warp_sum(v);
    if ((t & 31) == 0) red[t >> 5] = v;
    __syncthreads();
    if (t < 32) {
        float u = red[t];
        u = warp_sum(u);
        if (t == 0) red[32] = u;
    }
    __syncthreads();
    return red[32];
}

// ---------------- K1: h = Wc @ [x; read_prev] + bc --------------------------
__global__ void k_gemv_h(const float* __restrict__ x, const float* __restrict__ rp,
                         const float* __restrict__ Wc, const float* __restrict__ bc) {
    pdl_launch();
    int warp = (blockIdx.x * blockDim.x + threadIdx.x) >> 5;
    int lane = threadIdx.x & 31;
    if (warp >= D_CTRL) return;
    const float4* W4 = (const float4*)(Wc + (size_t)warp * D_CIN);
    const float4* x4 = (const float4*)x;
    const float4* r4 = (const float4*)rp;
    float s = 0.f;
    #pragma unroll
    for (int k = 0; k < 10; k++) {
        int c = lane + 32 * k;                 // float4 index 0..319
        float4 w = W4[c];
        float4 v = (c < 64) ? x4[c] : r4[c - 64];
        s += w.x * v.x + w.y * v.y + w.z * v.z + w.w * v.w;
    }
    s = warp_sum(s);
    if (lane == 0) g_h[warp] = s + bc[warp];
}

// ---------------- K2: p = Wp @ h + bp ; saida = sigmoid(Wo @ h + bo) ---------
// PDL: loads ALL weight regs before waiting on gemv_h.
__global__ void k_gemv_p(const float* __restrict__ Wp, const float* __restrict__ bp,
                         const float* __restrict__ Wo, const float* __restrict__ bo,
                         float* __restrict__ o_saida) {
    int warp = (blockIdx.x * blockDim.x + threadIdx.x) >> 5;
    int lane = threadIdx.x & 31;
    if (warp >= N_PAR + D_OUT) { pdl_wait(); return; }
    const float4* W4 = (warp < N_PAR)
        ? (const float4*)(Wp + (size_t)warp * D_CTRL)
        : (const float4*)(Wo + (size_t)(warp - N_PAR) * D_CTRL);
    float4 w[8];
    #pragma unroll
    for (int k = 0; k < 8; k++) w[k] = __ldcs(&W4[lane + 32 * k]);

    pdl_wait();

    const float4* h4 = (const float4*)g_h;
    float s = 0.f;
    #pragma unroll
    for (int k = 0; k < 8; k++) {
        float4 v = h4[lane + 32 * k];
        s += w[k].x * v.x + w[k].y * v.y + w[k].z * v.z + w[k].w * v.w;
    }
    s = warp_sum(s);
    if (lane == 0) {
        if (warp < N_PAR) g_p[warp] = s + bp[warp];
        else o_saida[warp - N_PAR] = sigmoidf_(s + bo[warp - N_PAR]);
    }
}

// ---------------- K3: activations, key normalization, scalars, reset reds ---
__global__ void k_activ() {
    pdl_launch();
    pdl_wait();
    __shared__ float red[33];
    int t = threadIdx.x;  // 1024 threads

    float kr = tanhf(g_p[t]);
    float nr = block_sum_1024(kr * kr, red);
    float kw = tanhf(g_p[HEADSZ + t]);
    float nw = block_sum_1024(kw * kw, red);

    g_krn[t] = kr / fmaxf(sqrtf(nr), 1e-12f);
    g_kwn[t] = kw / fmaxf(sqrtf(nw), 1e-12f);
    g_e[t]   = sigmoidf_(g_p[2 * HEADSZ + t]);
    g_a[t]   = tanhf(g_p[2 * HEADSZ + COLS + t]);

    if (t < 2) {
        int o = t * HEADSZ;
        float beta  = softplusf_(g_p[o + COLS]);
        float gg    = sigmoidf_(g_p[o + COLS + 1]);
        float a0 = g_p[o + COLS + 2], a1 = g_p[o + COLS + 3], a2 = g_p[o + COLS + 4];
        float m = fmaxf(a0, fmaxf(a1, a2));
        float e0 = expf(a0 - m), e1 = expf(a1 - m), e2 = expf(a2 - m);
        float inv = 1.f / (e0 + e1 + e2);
        float gamma = softplusf_(g_p[o + COLS + 5]) + 1.f;
        g_scal[t * 6 + 0] = beta;
        g_scal[t * 6 + 1] = gg;
        g_scal[t * 6 + 2] = e0 * inv;
        g_scal[t * 6 + 3] = e1 * inv;
        g_scal[t * 6 + 4] = e2 * inv;
        g_scal[t * 6 + 5] = gamma;
    }
    if (t < 4) g_red[t] = 0.f;
}

// ---------------- K4: similarity pass — cp.async self-staged -----------------
// Each warp owns 2 rows; each LANE cp.asyncs exactly the 16 float4s it will
// later read (row[lane+32k]) -> wait_group 0 is per-thread sufficient, no
// cross-thread handoff, no mbarrier, no syncthreads in the data path. All
// 64 KB of copies issued BEFORE pdl_wait (memoria is a kernel input), so the
// DMA ramps under k_activ. Regs ~32; loads never occupy warp issue slots.
__global__ void __launch_bounds__(256) k_sim(const float* __restrict__ mem) {
    extern __shared__ char sm[];
    __shared__ float ser[8], sew[8];
    pdl_launch();

    int t = threadIdx.x;
    int warp = t >> 5, lane = t & 31;
    int row0 = blockIdx.x * SIMB_ROWS + warp * 2;

    // issue this lane's own copies: 2 rows x 8 chunks of 16 B
    uint32_t smbase = smem_u32(sm);
    uint32_t d0 = smbase + warp * 8192;
    const char* g0 = (const char*)(mem + (size_t)row0 * COLS);
    #pragma unroll
    for (int r = 0; r < 2; r++) {
        #pragma unroll
        for (int k = 0; k < 8; k++) {
            uint32_t off = r * 4096 + (lane + 32 * k) * 16;
            cp_async16(d0 + off, g0 + off);
        }
    }
    asm volatile("cp.async.commit_group;" ::: "memory");

    pdl_wait();   // keys/scalars from k_activ must be complete

    // stage keys in smem (region above the 64 KB data)
    float4* skr = (float4*)(sm + SIMB_ROWS * 4096);
    float4* skw = skr + 256;
    skr[t] = ((const float4*)g_krn)[t];
    skw[t] = ((const float4*)g_kwn)[t];
    __syncthreads();

    asm volatile("cp.async.wait_group 0;" ::: "memory");

    const float4* myrows = (const float4*)(sm + warp * 8192);
    float br = g_scal[0], bw = g_scal[6];
    float sr = 0.f, sw = 0.f;

    #pragma unroll
    for (int r = 0; r < 2; r++) {
        float dr = 0.f, dw = 0.f, ss = 0.f;
        #pragma unroll
        for (int k = 0; k < 8; k++) {
            int c = lane + 32 * k;
            float4 v = myrows[r * 256 + c];
            float4 kr = skr[c], kw = skw[c];
            dr += v.x * kr.x + v.y * kr.y + v.z * kr.z + v.w * kr.w;
            dw += v.x * kw.x + v.y * kw.y + v.z * kw.z + v.w * kw.w;
            ss += v.x * v.x + v.y * v.y + v.z * v.z + v.w * v.w;
        }
        dr = warp_sum(dr); dw = warp_sum(dw); ss = warp_sum(ss);
        if (lane == 0) {
            float inv = 1.f / fmaxf(sqrtf(ss), 1e-12f);
            // z = beta*cos; subtract analytic bound beta (cos <= 1)
            float er = expf(br * dr * inv - br);
            float ew = expf(bw * dw * inv - bw);
            g_z[0][row0 + r] = er;
            g_z[1][row0 + r] = ew;
            sr += er; sw += ew;
        }
    }
    if (lane == 0) { ser[warp] = sr; sew[warp] = sw; }
    __syncthreads();
    if (t == 0) {
        float tsr = 0.f, tsw = 0.f;
        #pragma unroll
        for (int i = 0; i < 8; i++) { tsr += ser[i]; tsw += sew[i]; }
        atomicAdd(&g_red[0], tsr);
        atomicAdd(&g_red[1], tsw);
    }
}

// ---------------- K5: gate + circular shift + sharpening (both heads) -------
__global__ void k_shiftpow(const float* __restrict__ wpr, const float* __restrict__ wpw) {
    pdl_launch();   // k_final prologue reads only memoria
    __shared__ float red[8];
    int head = blockIdx.y;
    int i = blockIdx.x * 256 + threadIdx.x;
    const float* wprev = head ? wpw : wpr;
    int im = (i - 1) & (ROWS - 1), ip = (i + 1) & (ROWS - 1);
    float pvm = wprev[im], pv0 = wprev[i], pvp = wprev[ip];

    pdl_wait();

    const float* z = g_z[head];
    float invsum = 1.f / g_red[head];
    float gg = g_scal[head * 6 + 1];
    float s0 = g_scal[head * 6 + 2], s1 = g_scal[head * 6 + 3], s2 = g_scal[head * 6 + 4];
    float gamma = g_scal[head * 6 + 5];
    float omg = 1.f - gg;

    float wgm = gg * z[im] * invsum + omg * pvm;
    float wg0 = gg * z[i]  * invsum + omg * pv0;
    float wgp = gg * z[ip] * invsum + omg * pvp;
    float wt = s0 * wgm + s1 * wg0 + s2 * wgp;   // roll(+1)=i-1, roll(-1)=i+1
    float wp = powf(wt, gamma);
    g_wpow[head][i] = wp;

    wp = warp_sum(wp);
    if ((threadIdx.x & 31) == 0) red[threadIdx.x >> 5] = wp;
    __syncthreads();
    if (threadIdx.x == 0) {
        float s = 0.f;
        #pragma unroll
        for (int w = 0; w < 8; w++) s += red[w];
        atomicAdd(&g_red[2 + head], s);
    }
}

// ---------------- K6: final pass — pipelined LDG, thread-owns-columns -------
// Champion (R10, 84.2us). First 4-row prefetch hoisted above pdl_wait.
__global__ void __launch_bounds__(256) k_final(const float* __restrict__ mem,
                                               float* __restrict__ memnew,
                                               float* __restrict__ o_wr,
                                               float* __restrict__ o_ww) {
    int t = threadIdx.x;
    int row0 = blockIdx.x * RPB;
    const float4* m4 = (const float4*)mem + (size_t)row0 * 256 + t;
    float4* o4 = (float4*)memnew + (size_t)row0 * 256 + t;

    float4 buf[2][4];
    #pragma unroll
    for (int j = 0; j < 4; j++) buf[0][j] = __ldcs(m4 + (size_t)j * 256);

    pdl_wait();

    float inv_r = 1.f / (g_red[2] + 1e-8f);
    float inv_w = 1.f / (g_red[3] + 1e-8f);

    if (t < RPB) {
        int r = row0 + t;
        o_wr[r] = g_wpow[0][r] * inv_r;
        o_ww[r] = g_wpow[1][r] * inv_w;
    }

    float4 e = ((const float4*)g_e)[t];
    float4 a = ((const float4*)g_a)[t];
    float4 acc = make_float4(0.f, 0.f, 0.f, 0.f);

    #pragma unroll
    for (int r = 0; r < RPB; r += 4) {
        const int cur = (r >> 2) & 1, nxt = cur ^ 1;
        if (r + 4 < RPB) {
            #pragma unroll
            for (int j = 0; j < 4; j++)
                buf[nxt][j] = __ldcs(m4 + (size_t)(r + 4 + j) * 256);
        }
        #pragma unroll
        for (int j = 0; j < 4; j++) {
            int row = row0 + r + j;
            float wr = g_wpow[0][row] * inv_r;
            float ww = g_wpow[1][row] * inv_w;
            float4 m = buf[cur][j];
            float4 o;
            o.x = m.x * (1.f - ww * e.x) + ww * a.x;
            o.y = m.y * (1.f - ww * e.y) + ww * a.y;
            o.z = m.z * (1.f - ww * e.z) + ww * a.z;
            o.w = m.w * (1.f - ww * e.w) + ww * a.w;
            __stcs(o4 + (size_t)(r + j) * 256, o);
            acc.x += wr * m.x;
            acc.y += wr * m.y;
            acc.z += wr * m.z;
            acc.w += wr * m.w;
        }
    }
    ((float4*)g_part)[(size_t)blockIdx.x * 256 + t] = acc;
}

// ---------------- K7: reduce read_vec partials -------------------------------
__global__ void __launch_bounds__(256) k_rv(float* __restrict__ rv) {
    pdl_wait();
    __shared__ float4 sh[256];
    int b = blockIdx.x;      // 0..255
    int t = threadIdx.x;
    const float4* p4 = (const float4*)g_part;
    float4 s = make_float4(0.f, 0.f, 0.f, 0.f);
    #pragma unroll
    for (int i = 0; i < NBF / 256; i++) {
        float4 v = __ldcs(&p4[(size_t)(t + i * 256) * 256 + b]);
        s.x += v.x; s.y += v.y; s.z += v.z; s.w += v.w;
    }
    sh[t] = s;
    __syncthreads();
    #pragma unroll
    for (int off = 128; off >= 1; off >>= 1) {
        if (t < off) {
            float4 u = sh[t + off];
            sh[t].x += u.x; sh[t].y += u.y; sh[t].z += u.z; sh[t].w += u.w;
        }
        __syncthreads();
    }
    if (t == 0) ((float4*)rv)[b] = sh[0];
}

// ---------------- launcher ----------------------------------------------------
template <typename K, typename... Args>
static void launch_pdl(K kernel, dim3 grid, dim3 block, size_t smem, Args... args) {
    cudaLaunchConfig_t cfg = {};
    cfg.gridDim = grid;
    cfg.blockDim = block;
    cfg.dynamicSmemBytes = smem;
    cfg.stream = 0;
    cudaLaunchAttribute attr[1];
    attr[0].id = cudaLaunchAttributeProgrammaticStreamSerialization;
    attr[0].val.programmaticStreamSerializationAllowed = 1;
    cfg.attrs = attr;
    cfg.numAttrs = 1;
    cudaLaunchKernelEx(&cfg, kernel, args...);
}

extern "C" void kernel_launch(void* const* d_in, const int* in_sizes, int n_in,
                              void* d_out, int out_size) {
    const float* x   = (const float*)d_in[0];
    const float* mem = (const float*)d_in[1];
    const float* Wc  = (const float*)d_in[2];
    const float* bc  = (const float*)d_in[3];
    const float* Wp  = (const float*)d_in[4];
    const float* bp  = (const float*)d_in[5];
    const float* Wo  = (const float*)d_in[6];
    const float* bo  = (const float*)d_in[7];
    const float* rp  = (const float*)d_in[8];
    const float* wrp = (const float*)d_in[9];
    const float* wwp = (const float*)d_in[10];

    float* out     = (float*)d_out;
    float* o_saida = out;                                  // [256]
    float* o_mem   = out + D_OUT;                          // [32768*1024]
    float* o_rv    = o_mem + (size_t)ROWS * COLS;          // [1024]
    float* o_wr    = o_rv + COLS;                          // [32768]
    float* o_ww    = o_wr + ROWS;                          // [32768]

    cudaFuncSetAttribute(k_sim, cudaFuncAttributeMaxDynamicSharedMemorySize, SIM_SMEM);

    k_gemv_h<<<D_CTRL / 8, 256>>>(x, rp, Wc, bc);
    launch_pdl(k_gemv_p, dim3((N_PAR + D_OUT + 7) / 8), dim3(256), 0, Wp, bp, Wo, bo, o_saida);
    launch_pdl(k_activ, dim3(1), dim3(1024), 0);
    launch_pdl(k_sim, dim3(ROWS / SIMB_ROWS), dim3(256), (size_t)SIM_SMEM, mem);
    launch_pdl(k_shiftpow, dim3(ROWS / 256, 2), dim3(256), 0, wrp, wwp);
    launch_pdl(k_final, dim3(NBF), dim3(256), 0, mem, o_mem, o_wr, o_ww);
    launch_pdl(k_rv, dim3(COLS / 4), dim3(256), 0, o_rv);
}